// round 16
// baseline (speedup 1.0000x reference)
#include <cuda_runtime.h>
#include <cstdint>

#define HIDDEN 4096
#define NH 32
#define NKV 8
#define HD 128
#define BS 16
#define SEQ 4096
#define QKV_N 6144           // 4096 q + 1024 k + 1024 v
#define KSPLIT 16
#define KC (HIDDEN / KSPLIT) // 256
#define SPLITS 32
#define CHUNK (SEQ / SPLITS) // 128
#define WROWS 16             // rows per warp within chunk
#define NSTAGE 8             // WROWS / 2
#define DEPTH 2              // per-warp ring buffer depth (double buffer)
#define XSP 18               // padded row stride for xs (even -> f32x2 aligned)
#define WPF 8                // W prefetch depth (float2 entries)

// ---------------- scratch (device globals; no allocs allowed) ----------------
__device__ float g_qkvpart[KSPLIT][BS * QKV_N];  // GEMM partials for q|k|v
__device__ float g_q[BS * NH * HD];              // rope'd q
__device__ float g_k[BS * NKV * HD];             // rope'd new k
__device__ float g_v[BS * NKV * HD];             // new v
__device__ float g_pacc[BS * NKV * 4 * SPLITS * HD]; // flash partial accumulators
__device__ float g_pm[BS * NKV * 4 * SPLITS];        // partial max  [head][split]
__device__ float g_pl[BS * NKV * 4 * SPLITS];        // partial sum  [head][split]
__device__ float g_attn[BS * NH * HD];           // attention output pre-wo
__device__ float g_opart[KSPLIT][BS * HIDDEN];   // wo GEMM partials

__device__ __forceinline__ void cp16(void* smem_dst, const void* gsrc) {
    uint32_t s = (uint32_t)__cvta_generic_to_shared(smem_dst);
    asm volatile("cp.async.cg.shared.global [%0], [%1], 16;"
                 :: "r"(s), "l"(gsrc) : "memory");
}

__device__ __forceinline__ unsigned long long pack2(float w) {
    unsigned long long r;
    asm("mov.b64 %0, {%1, %1};" : "=l"(r) : "f"(w));
    return r;
}
__device__ __forceinline__ unsigned long long ffma2(unsigned long long x2,
                                                    unsigned long long w2,
                                                    unsigned long long a2) {
    unsigned long long r;
    asm("fma.rn.f32x2 %0, %1, %2, %3;" : "=l"(r) : "l"(x2), "l"(w2), "l"(a2));
    return r;
}

// ---------------- fused qkv skinny GEMM: 2 cols/thread, float2 W stream ----------------
// grid (QKV_N/256, KSPLIT) = (24,16), block 128. Each thread owns 2 adjacent
// columns; xs smem reads are shared across both columns (half the LDS per FLOP).
__global__ void qkv_gemm_kernel(const float* __restrict__ X,
                                const float* __restrict__ wq,
                                const float* __restrict__ wk,
                                const float* __restrict__ wv) {
    __shared__ float xs[KC][XSP];
    int n0 = blockIdx.x * 256 + 2 * threadIdx.x;   // first of 2 columns
    int k0 = blockIdx.y * KC;

    const float* W; int col, Nw;
    if (n0 < NH * HD)              { W = wq; col = n0;            Nw = NH * HD; }
    else if (n0 < (NH + NKV) * HD) { W = wk; col = n0 - NH * HD;  Nw = NKV * HD; }
    else                           { W = wv; col = n0 - (NH + NKV) * HD; Nw = NKV * HD; }

    for (int i = threadIdx.x; i < BS * KC; i += 128) {
        int b = i / KC, k = i % KC;
        xs[k][b] = X[b * HIDDEN + k0 + k];
    }
    __syncthreads();

    unsigned long long accA[8], accB[8];
#pragma unroll
    for (int p = 0; p < 8; p++) { accA[p] = 0ull; accB[p] = 0ull; }

    const float* Wp = W + (size_t)k0 * Nw + col;
    float2 wb[WPF];
#pragma unroll
    for (int i = 0; i < WPF; i++) wb[i] = __ldcs((const float2*)(Wp + (size_t)i * Nw));
#pragma unroll 1
    for (int k = 0; k < KC; k += WPF) {
        float2 nb[WPF];
        if (k + WPF < KC) {
            const float* Wn = Wp + (size_t)(k + WPF) * Nw;
#pragma unroll
            for (int i = 0; i < WPF; i++) nb[i] = __ldcs((const float2*)(Wn + (size_t)i * Nw));
        } else {
#pragma unroll
            for (int i = 0; i < WPF; i++) nb[i] = make_float2(0.f, 0.f);
        }
#pragma unroll
        for (int i = 0; i < WPF; i++) {
            unsigned long long wA = pack2(wb[i].x);
            unsigned long long wB = pack2(wb[i].y);
            const unsigned long long* xr = (const unsigned long long*)&xs[k + i][0];
#pragma unroll
            for (int p = 0; p < 8; p++) {
                unsigned long long x2 = xr[p];
                accA[p] = ffma2(x2, wA, accA[p]);
                accB[p] = ffma2(x2, wB, accB[p]);
            }
        }
#pragma unroll
        for (int i = 0; i < WPF; i++) wb[i] = nb[i];
    }

    size_t base = (size_t)blockIdx.y * BS * QKV_N;
#pragma unroll
    for (int p = 0; p < 8; p++) {
        float aLo, aHi, bLo, bHi;
        asm("mov.b64 {%0, %1}, %2;" : "=f"(aLo), "=f"(aHi) : "l"(accA[p]));
        asm("mov.b64 {%0, %1}, %2;" : "=f"(bLo), "=f"(bHi) : "l"(accB[p]));
        *(float2*)&g_qkvpart[0][base + (size_t)(2 * p) * QKV_N + n0]     = make_float2(aLo, bLo);
        *(float2*)&g_qkvpart[0][base + (size_t)(2 * p + 1) * QKV_N + n0] = make_float2(aHi, bHi);
    }
}

// ---------------- wo skinny GEMM: 2 cols/thread, float2 W stream ----------------
// grid (HIDDEN/256, KSPLIT) = (16,16), block 128.
__global__ void wo_gemm_kernel(const float* __restrict__ W) {
    __shared__ float xs[KC][XSP];
    int n0 = blockIdx.x * 256 + 2 * threadIdx.x;
    int k0 = blockIdx.y * KC;

    for (int i = threadIdx.x; i < BS * KC; i += 128) {
        int b = i / KC, k = i % KC;
        xs[k][b] = g_attn[b * HIDDEN + k0 + k];
    }
    __syncthreads();

    unsigned long long accA[8], accB[8];
#pragma unroll
    for (int p = 0; p < 8; p++) { accA[p] = 0ull; accB[p] = 0ull; }

    const float* Wp = W + (size_t)k0 * HIDDEN + n0;
    float2 wb[WPF];
#pragma unroll
    for (int i = 0; i < WPF; i++) wb[i] = __ldcs((const float2*)(Wp + (size_t)i * HIDDEN));
#pragma unroll 1
    for (int k = 0; k < KC; k += WPF) {
        float2 nb[WPF];
        if (k + WPF < KC) {
            const float* Wn = Wp + (size_t)(k + WPF) * HIDDEN;
#pragma unroll
            for (int i = 0; i < WPF; i++) nb[i] = __ldcs((const float2*)(Wn + (size_t)i * HIDDEN));
        } else {
#pragma unroll
            for (int i = 0; i < WPF; i++) nb[i] = make_float2(0.f, 0.f);
        }
#pragma unroll
        for (int i = 0; i < WPF; i++) {
            unsigned long long wA = pack2(wb[i].x);
            unsigned long long wB = pack2(wb[i].y);
            const unsigned long long* xr = (const unsigned long long*)&xs[k + i][0];
#pragma unroll
            for (int p = 0; p < 8; p++) {
                unsigned long long x2 = xr[p];
                accA[p] = ffma2(x2, wA, accA[p]);
                accB[p] = ffma2(x2, wB, accB[p]);
            }
        }
#pragma unroll
        for (int i = 0; i < WPF; i++) wb[i] = nb[i];
    }

    size_t base = (size_t)blockIdx.y * BS * HIDDEN;
#pragma unroll
    for (int p = 0; p < 8; p++) {
        float aLo, aHi, bLo, bHi;
        asm("mov.b64 {%0, %1}, %2;" : "=f"(aLo), "=f"(aHi) : "l"(accA[p]));
        asm("mov.b64 {%0, %1}, %2;" : "=f"(bLo), "=f"(bHi) : "l"(accB[p]));
        *(float2*)&g_opart[0][base + (size_t)(2 * p) * HIDDEN + n0]     = make_float2(aLo, bLo);
        *(float2*)&g_opart[0][base + (size_t)(2 * p + 1) * HIDDEN + n0] = make_float2(aHi, bHi);
    }
}

// ---------------- parallel reduce partials + RoPE + stage q/k/v ----------------
__global__ void rope_reduce_kernel(const float* __restrict__ rope_cache,
                                   const int* __restrict__ last_pos) {
    int idx = blockIdx.x * 256 + threadIdx.x;       // pair index
    int b = idx / (QKV_N / 2);
    int i = (idx % (QKV_N / 2)) * 2;

    float v0 = 0.f, v1 = 0.f;
#pragma unroll
    for (int ks = 0; ks < KSPLIT; ks++) {
        const float2 s = __ldcs((const float2*)&g_qkvpart[ks][b * QKV_N + i]);
        v0 += s.x; v1 += s.y;
    }

    float o0 = v0, o1 = v1;
    if (i < (NH + NKV) * HD) {   // rope on q and k
        int lp = last_pos[b];
        int pi = (i % HD) >> 1;
        const float2 cs = *(const float2*)(rope_cache + (size_t)lp * HD + 2 * pi);
        o0 = v0 * cs.x - v1 * cs.y;
        o1 = v1 * cs.x + v0 * cs.y;
    }

    float* dst;
    if (i < NH * HD)                 dst = g_q + b * (NH * HD) + i;
    else if (i < (NH + NKV) * HD)    dst = g_k + b * (NKV * HD) + (i - NH * HD);
    else                             dst = g_v + b * (NKV * HD) + (i - (NH + NKV) * HD);
    dst[0] = o0;
    dst[1] = o1;
}

// ---------------- per-warp-pipelined fused cache-copy + online-softmax decode ----------------
// grid (SPLITS, NKV, BS) = 4096 blocks, 256 threads (8 warps).
__global__ void __launch_bounds__(256, 4)
attn_kernel(const float* __restrict__ cache_k,
            const float* __restrict__ cache_v,
            const float* __restrict__ mask,
            const int* __restrict__ last_pos,
            float* __restrict__ out_k, float* __restrict__ out_v) {
    extern __shared__ float4 dsm[];
    float4* kb = dsm;                              // [8][DEPTH][2][32] float4 = 16 KB
    float4* vb = dsm + 8 * DEPTH * 2 * 32;         // 16 KB
    float*  sq = (float*)(dsm + 2 * 8 * DEPTH * 2 * 32);  // 2 KB
    __shared__ float smx[8][4], slx[8][4];

    int sp = blockIdx.x, kv = blockIdx.y, b = blockIdx.z;
    int tid = threadIdx.x;
    int j0 = sp * CHUNK;
    int lp = last_pos[b];
    int w = tid >> 5, l = tid & 31;

    const float* newk = g_k + (b * NKV + kv) * HD;
    const float* newv = g_v + (b * NKV + kv) * HD;
    const size_t cbase = ((size_t)b * SEQ) * (NKV * HD) + (size_t)kv * HD;
    const int jw = j0 + w * WROWS;                 // this warp's first row

    float4* kbw = kb + (size_t)w * (DEPTH * 2 * 32);
    float4* vbw = vb + (size_t)w * (DEPTH * 2 * 32);

    auto load_stage = [&](int st) {
        int buf = st & (DEPTH - 1);
        int j = jw + 2 * st;
        const float* k0s = (j == lp)     ? (newk + l * 4)
                          : (cache_k + cbase + (size_t)j * (NKV * HD) + l * 4);
        const float* k1s = (j + 1 == lp) ? (newk + l * 4)
                          : (cache_k + cbase + (size_t)(j + 1) * (NKV * HD) + l * 4);
        const float* v0s = (j == lp)     ? (newv + l * 4)
                          : (cache_v + cbase + (size_t)j * (NKV * HD) + l * 4);
        const float* v1s = (j + 1 == lp) ? (newv + l * 4)
                          : (cache_v + cbase + (size_t)(j + 1) * (NKV * HD) + l * 4);
        cp16(&kbw[(buf * 2 + 0) * 32 + l], k0s);
        cp16(&kbw[(buf * 2 + 1) * 32 + l], k1s);
        cp16(&vbw[(buf * 2 + 0) * 32 + l], v0s);
        cp16(&vbw[(buf * 2 + 1) * 32 + l], v1s);
        asm volatile("cp.async.commit_group;" ::: "memory");
    };

    load_stage(0);
    load_stage(1);

    for (int i = tid; i < 4 * HD; i += 256) {
        int h = i / HD, d = i % HD;
        sq[h * HD + d] = g_q[b * (NH * HD) + (kv * 4 + h) * HD + d];
    }
    __syncthreads();   // sq visible to all warps

    const float scale = 0.08838834764831845f; // 1/sqrt(128)
    float4 acc[4];
    float m[4], lsum[4];
#pragma unroll
    for (int h = 0; h < 4; h++) {
        acc[h] = make_float4(0.f, 0.f, 0.f, 0.f);
        m[h] = -1e30f;
        lsum[h] = 0.f;
    }

#pragma unroll 1
    for (int t = 0; t < NSTAGE; t++) {
        if (t < NSTAGE - 1) asm volatile("cp.async.wait_group 1;" ::: "memory");
        else                asm volatile("cp.async.wait_group 0;" ::: "memory");

        int jb = jw + 2 * t;
        float2 mq = __ldg((const float2*)(mask + b * SEQ + jb));

        int buf = t & (DEPTH - 1);
        float4 k0r = kbw[(buf * 2 + 0) * 32 + l];
        float4 k1r = kbw[(buf * 2 + 1) * 32 + l];
        float4 v0r = vbw[(buf * 2 + 0) * 32 + l];
        float4 v1r = vbw[(buf * 2 + 1) * 32 + l];

        if (t + 2 < NSTAGE) load_stage(t + 2);   // refill the buf just consumed

        size_t row0 = cbase + (size_t)jb * (NKV * HD);
        __stcs((float4*)(out_k + row0) + l, k0r);
        __stcs((float4*)(out_k + row0 + (size_t)(NKV * HD)) + l, k1r);
        __stcs((float4*)(out_v + row0) + l, v0r);
        __stcs((float4*)(out_v + row0 + (size_t)(NKV * HD)) + l, v1r);

        float s0[4], s1[4];
#pragma unroll
        for (int h = 0; h < 4; h++) {
            float4 q = *(float4*)&sq[h * HD + 4 * l];
            s0[h] = q.x * k0r.x + q.y * k0r.y + q.z * k0r.z + q.w * k0r.w;
            s1[h] = q.x * k1r.x + q.y * k1r.y + q.z * k1r.z + q.w * k1r.w;
        }
#pragma unroll
        for (int offx = 16; offx; offx >>= 1) {
#pragma unroll
            for (int h = 0; h < 4; h++) {
                s0[h] += __shfl_xor_sync(0xffffffffu, s0[h], offx);
                s1[h] += __shfl_xor_sync(0xffffffffu, s1[h], offx);
            }
        }

#pragma unroll
        for (int h = 0; h < 4; h++) {
            float sc0 = s0[h] * scale + mq.x;
            float sc1 = s1[h] * scale + mq.y;
            float newm = fmaxf(m[h], fmaxf(sc0, sc1));
            if (newm > m[h]) {                    // warp-uniform branch
                float fac = __expf(m[h] - newm);
                lsum[h] *= fac;
                acc[h].x *= fac; acc[h].y *= fac; acc[h].z *= fac; acc[h].w *= fac;
                m[h] = newm;
            }
            float p0 = __expf(sc0 - m[h]);
            float p1 = __expf(sc1 - m[h]);
            lsum[h] += p0 + p1;
            acc[h].x = fmaf(p0, v0r.x, fmaf(p1, v1r.x, acc[h].x));
            acc[h].y = fmaf(p0, v0r.y, fmaf(p1, v1r.y, acc[h].y));
            acc[h].z = fmaf(p0, v0r.z, fmaf(p1, v1r.z, acc[h].z));
            acc[h].w = fmaf(p0, v0r.w, fmaf(p1, v1r.w, acc[h].w));
        }
    }

    // ---- combine the 8 warp partials (sacc aliases each warp's OWN kb region) ----
    float* saccw = (float*)(kb + (size_t)w * (DEPTH * 2 * 32));
#pragma unroll
    for (int h = 0; h < 4; h++)
        *(float4*)&saccw[h * HD + 4 * l] = acc[h];
    if (l == 0) {
#pragma unroll
        for (int h = 0; h < 4; h++) { smx[w][h] = m[h]; slx[w][h] = lsum[h]; }
    }
    __syncthreads();

    size_t hbase = (size_t)(b * NKV + kv) * 4;
    for (int o = tid; o < 4 * HD; o += 256) {
        int h = o / HD, d = o % HD;
        float M = -1e30f;
#pragma unroll
        for (int ww = 0; ww < 8; ww++) M = fmaxf(M, smx[ww][h]);
        float L = 0.f, s = 0.f;
#pragma unroll
        for (int ww = 0; ww < 8; ww++) {
            float fac = __expf(smx[ww][h] - M);
            s += ((float*)(kb + (size_t)ww * (DEPTH * 2 * 32)))[h * HD + d] * fac;
            L += slx[ww][h] * fac;
        }
        g_pacc[(((hbase + h) * SPLITS) + sp) * HD + d] = s;
        if (d == 0) {
            g_pm[(hbase + h) * SPLITS + sp] = M;
            g_pl[(hbase + h) * SPLITS + sp] = L;
        }
    }
}

// ---------------- combine split partials (split-parallel) ----------------
#define SGRP 8
#define SPG (SPLITS / SGRP)   // 4 splits per group
__global__ void combine_kernel() {
    __shared__ float sM[SGRP], sL[SGRP], sacc[SGRP][HD];

    int h = blockIdx.x, b = blockIdx.y;
    int d = threadIdx.x, sg = threadIdx.y;
    int kv = h >> 2, r = h & 3;
    size_t hb = ((size_t)(b * NKV + kv) * 4 + r);
    const float* pm = g_pm + hb * SPLITS + sg * SPG;
    const float* pl = g_pl + hb * SPLITS + sg * SPG;
    const float* pa = g_pacc + (hb * SPLITS + sg * SPG) * HD + d;

    float M = -1e30f;
#pragma unroll
    for (int s = 0; s < SPG; s++) M = fmaxf(M, pm[s]);
    float L = 0.f, acc = 0.f;
#pragma unroll
    for (int s = 0; s < SPG; s++) {
        float wgt = __expf(pm[s] - M);
        L += pl[s] * wgt;
        acc = fmaf(__ldcs(pa + (size_t)s * HD), wgt, acc);
    }
    sacc[sg][d] = acc;
    if (d == 0) { sM[sg] = M; sL[sg] = L; }
    __syncthreads();

    if (sg == 0) {
        float Mg = -1e30f;
#pragma unroll
        for (int g2 = 0; g2 < SGRP; g2++) Mg = fmaxf(Mg, sM[g2]);
        float Lg = 0.f, a = 0.f;
#pragma unroll
        for (int g2 = 0; g2 < SGRP; g2++) {
            float f = __expf(sM[g2] - Mg);
            Lg += sL[g2] * f;
            a = fmaf(sacc[g2][d], f, a);
        }
        g_attn[b * (NH * HD) + h * HD + d] = a / Lg;
    }
}

// ---------------- reduce wo-GEMM partials -> final out ----------------
__global__ void reduce_out_kernel(float* __restrict__ out) {
    int i = (blockIdx.x * 256 + threadIdx.x) * 4;
    float4 s = make_float4(0.f, 0.f, 0.f, 0.f);
#pragma unroll
    for (int ks = 0; ks < KSPLIT; ks++) {
        float4 p = __ldcs((const float4*)&g_opart[ks][i]);
        s.x += p.x; s.y += p.y; s.z += p.z; s.w += p.w;
    }
    *(float4*)(out + i) = s;
}

// ---------------- launch ----------------
extern "C" void kernel_launch(void* const* d_in, const int* in_sizes, int n_in,
                              void* d_out, int out_size) {
    const float* x       = (const float*)d_in[0];
    const float* mask    = (const float*)d_in[1];
    const float* rope    = (const float*)d_in[2];
    const float* wq      = (const float*)d_in[3];
    const float* wk      = (const float*)d_in[4];
    const float* wv      = (const float*)d_in[5];
    const float* wo      = (const float*)d_in[6];
    const float* cache_k = (const float*)d_in[7];
    const float* cache_v = (const float*)d_in[8];
    const int*   last_pos = (const int*)d_in[9];

    float* out   = (float*)d_out;
    float* out_k = out + (size_t)BS * HIDDEN;
    float* out_v = out_k + (size_t)BS * SEQ * NKV * HD;

    const int smem_bytes = 2 * 8 * DEPTH * 2 * 32 * 16 + 4 * HD * 4;  // 34 KB
    static int attr_set = 0;
    if (!attr_set) {
        cudaFuncSetAttribute(attn_kernel, cudaFuncAttributeMaxDynamicSharedMemorySize, smem_bytes);
        attr_set = 1;
    }

    qkv_gemm_kernel<<<dim3(QKV_N / 256, KSPLIT), 128>>>(x, wq, wk, wv);
    rope_reduce_kernel<<<(BS * QKV_N / 2) / 256, 256>>>(rope, last_pos);
    attn_kernel<<<dim3(SPLITS, NKV, BS), 256, smem_bytes>>>(cache_k, cache_v, mask, last_pos, out_k, out_v);
    combine_kernel<<<dim3(NH, BS), dim3(HD, SGRP)>>>();
    wo_gemm_kernel<<<dim3(HIDDEN / 256, KSPLIT), 128>>>(wo);
    reduce_out_kernel<<<(BS * HIDDEN / 4) / 256, 256>>>(out);
}

// round 17
// speedup vs baseline: 1.0184x; 1.0184x over previous
#include <cuda_runtime.h>
#include <cstdint>

#define HIDDEN 4096
#define NH 32
#define NKV 8
#define HD 128
#define BS 16
#define SEQ 4096
#define QKV_N 6144           // 4096 q + 1024 k + 1024 v
#define KSPLIT 16
#define KC (HIDDEN / KSPLIT) // 256
#define SPLITS 32
#define CHUNK (SEQ / SPLITS) // 128
#define WROWS 16             // rows per warp within chunk
#define NSTAGE 8             // WROWS / 2
#define DEPTH 2              // per-warp ring buffer depth (double buffer)
#define XSP 18               // padded row stride for xs (even -> f32x2 aligned)
#define WPF 16               // W prefetch depth

// ---------------- scratch (device globals; no allocs allowed) ----------------
__device__ float g_qkvpart[KSPLIT][BS * QKV_N];  // GEMM partials for q|k|v
__device__ float g_q[BS * NH * HD];              // rope'd q
__device__ float g_k[BS * NKV * HD];             // rope'd new k
__device__ float g_v[BS * NKV * HD];             // new v
__device__ float g_pacc[BS * NKV * 4 * SPLITS * HD]; // flash partial accumulators
__device__ float g_pm[BS * NKV * 4 * SPLITS];        // partial max  [head][split]
__device__ float g_pl[BS * NKV * 4 * SPLITS];        // partial sum  [head][split]
__device__ float g_attn[BS * NH * HD];           // attention output pre-wo
__device__ float g_opart[KSPLIT][BS * HIDDEN];   // wo GEMM partials

__device__ __forceinline__ void cp16(void* smem_dst, const void* gsrc) {
    uint32_t s = (uint32_t)__cvta_generic_to_shared(smem_dst);
    asm volatile("cp.async.cg.shared.global [%0], [%1], 16;"
                 :: "r"(s), "l"(gsrc) : "memory");
}

__device__ __forceinline__ unsigned long long pack2(float w) {
    unsigned long long r;
    asm("mov.b64 %0, {%1, %1};" : "=l"(r) : "f"(w));
    return r;
}
__device__ __forceinline__ unsigned long long ffma2(unsigned long long x2,
                                                    unsigned long long w2,
                                                    unsigned long long a2) {
    unsigned long long r;
    asm("fma.rn.f32x2 %0, %1, %2, %3;" : "=l"(r) : "l"(x2), "l"(w2), "l"(a2));
    return r;
}

// ---------------- fused qkv skinny GEMM (f32x2 packed): [16 x 4096] @ [4096 x 6144] ----------------
__global__ void qkv_gemm_kernel(const float* __restrict__ X,
                                const float* __restrict__ wq,
                                const float* __restrict__ wk,
                                const float* __restrict__ wv) {
    __shared__ float xs[KC][XSP];
    int ng = blockIdx.x * 128 + threadIdx.x;   // global col in [0, 6144)
    int k0 = blockIdx.y * KC;

    const float* W; int col, Nw;
    if (ng < NH * HD)              { W = wq; col = ng;            Nw = NH * HD; }
    else if (ng < (NH + NKV) * HD) { W = wk; col = ng - NH * HD;  Nw = NKV * HD; }
    else                           { W = wv; col = ng - (NH + NKV) * HD; Nw = NKV * HD; }

    for (int i = threadIdx.x; i < BS * KC; i += 128) {
        int b = i / KC, k = i % KC;
        xs[k][b] = X[b * HIDDEN + k0 + k];
    }
    __syncthreads();

    unsigned long long acc2[8];
#pragma unroll
    for (int p = 0; p < 8; p++) acc2[p] = 0ull;

    const float* Wp = W + (size_t)k0 * Nw + col;
    float wb[WPF];
#pragma unroll
    for (int i = 0; i < WPF; i++) wb[i] = __ldcs(Wp + (size_t)i * Nw);
#pragma unroll 1
    for (int k = 0; k < KC; k += WPF) {
        float nb[WPF];
        if (k + WPF < KC) {
            const float* Wn = Wp + (size_t)(k + WPF) * Nw;
#pragma unroll
            for (int i = 0; i < WPF; i++) nb[i] = __ldcs(Wn + (size_t)i * Nw);
        } else {
#pragma unroll
            for (int i = 0; i < WPF; i++) nb[i] = 0.f;
        }
#pragma unroll
        for (int i = 0; i < WPF; i++) {
            unsigned long long w2 = pack2(wb[i]);
            const unsigned long long* xr = (const unsigned long long*)&xs[k + i][0];
#pragma unroll
            for (int p = 0; p < 8; p++) acc2[p] = ffma2(xr[p], w2, acc2[p]);
        }
#pragma unroll
        for (int i = 0; i < WPF; i++) wb[i] = nb[i];
    }

    size_t base = (size_t)blockIdx.y * BS * QKV_N;
#pragma unroll
    for (int p = 0; p < 8; p++) {
        float lo, hi;
        asm("mov.b64 {%0, %1}, %2;" : "=f"(lo), "=f"(hi) : "l"(acc2[p]));
        g_qkvpart[0][base + (size_t)(2 * p) * QKV_N + ng]     = lo;
        g_qkvpart[0][base + (size_t)(2 * p + 1) * QKV_N + ng] = hi;
    }
}

// ---------------- wo skinny GEMM (f32x2 packed): g_attn [16 x 4096] @ wo [4096 x 4096] ----------------
__global__ void wo_gemm_kernel(const float* __restrict__ W) {
    __shared__ float xs[KC][XSP];
    int n = blockIdx.x * 128 + threadIdx.x;
    int k0 = blockIdx.y * KC;

    for (int i = threadIdx.x; i < BS * KC; i += 128) {
        int b = i / KC, k = i % KC;
        xs[k][b] = g_attn[b * HIDDEN + k0 + k];
    }
    __syncthreads();

    unsigned long long acc2[8];
#pragma unroll
    for (int p = 0; p < 8; p++) acc2[p] = 0ull;

    const float* Wp = W + (size_t)k0 * HIDDEN + n;
    float wb[WPF];
#pragma unroll
    for (int i = 0; i < WPF; i++) wb[i] = __ldcs(Wp + (size_t)i * HIDDEN);
#pragma unroll 1
    for (int k = 0; k < KC; k += WPF) {
        float nb[WPF];
        if (k + WPF < KC) {
            const float* Wn = Wp + (size_t)(k + WPF) * HIDDEN;
#pragma unroll
            for (int i = 0; i < WPF; i++) nb[i] = __ldcs(Wn + (size_t)i * HIDDEN);
        } else {
#pragma unroll
            for (int i = 0; i < WPF; i++) nb[i] = 0.f;
        }
#pragma unroll
        for (int i = 0; i < WPF; i++) {
            unsigned long long w2 = pack2(wb[i]);
            const unsigned long long* xr = (const unsigned long long*)&xs[k + i][0];
#pragma unroll
            for (int p = 0; p < 8; p++) acc2[p] = ffma2(xr[p], w2, acc2[p]);
        }
#pragma unroll
        for (int i = 0; i < WPF; i++) wb[i] = nb[i];
    }

    size_t base = (size_t)blockIdx.y * BS * HIDDEN;
#pragma unroll
    for (int p = 0; p < 8; p++) {
        float lo, hi;
        asm("mov.b64 {%0, %1}, %2;" : "=f"(lo), "=f"(hi) : "l"(acc2[p]));
        g_opart[0][base + (size_t)(2 * p) * HIDDEN + n]     = lo;
        g_opart[0][base + (size_t)(2 * p + 1) * HIDDEN + n] = hi;
    }
}

// ---------------- parallel reduce partials + RoPE + stage q/k/v ----------------
__global__ void rope_reduce_kernel(const float* __restrict__ rope_cache,
                                   const int* __restrict__ last_pos) {
    int idx = blockIdx.x * 256 + threadIdx.x;       // pair index
    int b = idx / (QKV_N / 2);
    int i = (idx % (QKV_N / 2)) * 2;

    float v0 = 0.f, v1 = 0.f;
#pragma unroll
    for (int ks = 0; ks < KSPLIT; ks++) {
        const float2 s = __ldcs((const float2*)&g_qkvpart[ks][b * QKV_N + i]);
        v0 += s.x; v1 += s.y;
    }

    float o0 = v0, o1 = v1;
    if (i < (NH + NKV) * HD) {   // rope on q and k
        int lp = last_pos[b];
        int pi = (i % HD) >> 1;
        const float2 cs = *(const float2*)(rope_cache + (size_t)lp * HD + 2 * pi);
        o0 = v0 * cs.x - v1 * cs.y;
        o1 = v1 * cs.x + v0 * cs.y;
    }

    float* dst;
    if (i < NH * HD)                 dst = g_q + b * (NH * HD) + i;
    else if (i < (NH + NKV) * HD)    dst = g_k + b * (NKV * HD) + (i - NH * HD);
    else                             dst = g_v + b * (NKV * HD) + (i - (NH + NKV) * HD);
    dst[0] = o0;
    dst[1] = o1;
}

// ---------------- per-warp-pipelined fused cache-copy + online-softmax decode ----------------
// grid (SPLITS, NKV, BS) = 4096 blocks, 256 threads (8 warps).
__global__ void __launch_bounds__(256, 4)
attn_kernel(const float* __restrict__ cache_k,
            const float* __restrict__ cache_v,
            const float* __restrict__ mask,
            const int* __restrict__ last_pos,
            float* __restrict__ out_k, float* __restrict__ out_v) {
    extern __shared__ float4 dsm[];
    float4* kb = dsm;                              // [8][DEPTH][2][32] float4 = 16 KB
    float4* vb = dsm + 8 * DEPTH * 2 * 32;         // 16 KB
    float*  sq = (float*)(dsm + 2 * 8 * DEPTH * 2 * 32);  // 2 KB
    __shared__ float smx[8][4], slx[8][4];

    int sp = blockIdx.x, kv = blockIdx.y, b = blockIdx.z;
    int tid = threadIdx.x;
    int j0 = sp * CHUNK;
    int lp = last_pos[b];
    int w = tid >> 5, l = tid & 31;

    const float* newk = g_k + (b * NKV + kv) * HD;
    const float* newv = g_v + (b * NKV + kv) * HD;
    const size_t cbase = ((size_t)b * SEQ) * (NKV * HD) + (size_t)kv * HD;
    const int jw = j0 + w * WROWS;                 // this warp's first row

    float4* kbw = kb + (size_t)w * (DEPTH * 2 * 32);
    float4* vbw = vb + (size_t)w * (DEPTH * 2 * 32);

    auto load_stage = [&](int st) {
        int buf = st & (DEPTH - 1);
        int j = jw + 2 * st;
        const float* k0s = (j == lp)     ? (newk + l * 4)
                          : (cache_k + cbase + (size_t)j * (NKV * HD) + l * 4);
        const float* k1s = (j + 1 == lp) ? (newk + l * 4)
                          : (cache_k + cbase + (size_t)(j + 1) * (NKV * HD) + l * 4);
        const float* v0s = (j == lp)     ? (newv + l * 4)
                          : (cache_v + cbase + (size_t)j * (NKV * HD) + l * 4);
        const float* v1s = (j + 1 == lp) ? (newv + l * 4)
                          : (cache_v + cbase + (size_t)(j + 1) * (NKV * HD) + l * 4);
        cp16(&kbw[(buf * 2 + 0) * 32 + l], k0s);
        cp16(&kbw[(buf * 2 + 1) * 32 + l], k1s);
        cp16(&vbw[(buf * 2 + 0) * 32 + l], v0s);
        cp16(&vbw[(buf * 2 + 1) * 32 + l], v1s);
        asm volatile("cp.async.commit_group;" ::: "memory");
    };

    load_stage(0);
    load_stage(1);

    for (int i = tid; i < 4 * HD; i += 256) {
        int h = i / HD, d = i % HD;
        sq[h * HD + d] = g_q[b * (NH * HD) + (kv * 4 + h) * HD + d];
    }
    __syncthreads();   // sq visible to all warps

    const float scale = 0.08838834764831845f; // 1/sqrt(128)
    float4 acc[4];
    float m[4], lsum[4];
#pragma unroll
    for (int h = 0; h < 4; h++) {
        acc[h] = make_float4(0.f, 0.f, 0.f, 0.f);
        m[h] = -1e30f;
        lsum[h] = 0.f;
    }

#pragma unroll 1
    for (int t = 0; t < NSTAGE; t++) {
        if (t < NSTAGE - 1) asm volatile("cp.async.wait_group 1;" ::: "memory");
        else                asm volatile("cp.async.wait_group 0;" ::: "memory");

        int jb = jw + 2 * t;
        float2 mq = __ldg((const float2*)(mask + b * SEQ + jb));

        int buf = t & (DEPTH - 1);
        float4 k0r = kbw[(buf * 2 + 0) * 32 + l];
        float4 k1r = kbw[(buf * 2 + 1) * 32 + l];
        float4 v0r = vbw[(buf * 2 + 0) * 32 + l];
        float4 v1r = vbw[(buf * 2 + 1) * 32 + l];

        if (t + 2 < NSTAGE) load_stage(t + 2);   // refill the buf just consumed

        size_t row0 = cbase + (size_t)jb * (NKV * HD);
        __stcs((float4*)(out_k + row0) + l, k0r);
        __stcs((float4*)(out_k + row0 + (size_t)(NKV * HD)) + l, k1r);
        __stcs((float4*)(out_v + row0) + l, v0r);
        __stcs((float4*)(out_v + row0 + (size_t)(NKV * HD)) + l, v1r);

        float s0[4], s1[4];
#pragma unroll
        for (int h = 0; h < 4; h++) {
            float4 q = *(float4*)&sq[h * HD + 4 * l];
            s0[h] = q.x * k0r.x + q.y * k0r.y + q.z * k0r.z + q.w * k0r.w;
            s1[h] = q.x * k1r.x + q.y * k1r.y + q.z * k1r.z + q.w * k1r.w;
        }
#pragma unroll
        for (int offx = 16; offx; offx >>= 1) {
#pragma unroll
            for (int h = 0; h < 4; h++) {
                s0[h] += __shfl_xor_sync(0xffffffffu, s0[h], offx);
                s1[h] += __shfl_xor_sync(0xffffffffu, s1[h], offx);
            }
        }

#pragma unroll
        for (int h = 0; h < 4; h++) {
            float sc0 = s0[h] * scale + mq.x;
            float sc1 = s1[h] * scale + mq.y;
            float newm = fmaxf(m[h], fmaxf(sc0, sc1));
            if (newm > m[h]) {                    // warp-uniform branch
                float fac = __expf(m[h] - newm);
                lsum[h] *= fac;
                acc[h].x *= fac; acc[h].y *= fac; acc[h].z *= fac; acc[h].w *= fac;
                m[h] = newm;
            }
            float p0 = __expf(sc0 - m[h]);
            float p1 = __expf(sc1 - m[h]);
            lsum[h] += p0 + p1;
            acc[h].x = fmaf(p0, v0r.x, fmaf(p1, v1r.x, acc[h].x));
            acc[h].y = fmaf(p0, v0r.y, fmaf(p1, v1r.y, acc[h].y));
            acc[h].z = fmaf(p0, v0r.z, fmaf(p1, v1r.z, acc[h].z));
            acc[h].w = fmaf(p0, v0r.w, fmaf(p1, v1r.w, acc[h].w));
        }
    }

    // ---- combine the 8 warp partials (sacc aliases each warp's OWN kb region) ----
    float* saccw = (float*)(kb + (size_t)w * (DEPTH * 2 * 32));
#pragma unroll
    for (int h = 0; h < 4; h++)
        *(float4*)&saccw[h * HD + 4 * l] = acc[h];
    if (l == 0) {
#pragma unroll
        for (int h = 0; h < 4; h++) { smx[w][h] = m[h]; slx[w][h] = lsum[h]; }
    }
    __syncthreads();

    size_t hbase = (size_t)(b * NKV + kv) * 4;
    for (int o = tid; o < 4 * HD; o += 256) {
        int h = o / HD, d = o % HD;
        float M = -1e30f;
#pragma unroll
        for (int ww = 0; ww < 8; ww++) M = fmaxf(M, smx[ww][h]);
        float L = 0.f, s = 0.f;
#pragma unroll
        for (int ww = 0; ww < 8; ww++) {
            float fac = __expf(smx[ww][h] - M);
            s += ((float*)(kb + (size_t)ww * (DEPTH * 2 * 32)))[h * HD + d] * fac;
            L += slx[ww][h] * fac;
        }
        g_pacc[(((hbase + h) * SPLITS) + sp) * HD + d] = s;
        if (d == 0) {
            g_pm[(hbase + h) * SPLITS + sp] = M;
            g_pl[(hbase + h) * SPLITS + sp] = L;
        }
    }
}

// ---------------- combine split partials (split-parallel) ----------------
#define SGRP 8
#define SPG (SPLITS / SGRP)   // 4 splits per group
__global__ void combine_kernel() {
    __shared__ float sM[SGRP], sL[SGRP], sacc[SGRP][HD];

    int h = blockIdx.x, b = blockIdx.y;
    int d = threadIdx.x, sg = threadIdx.y;
    int kv = h >> 2, r = h & 3;
    size_t hb = ((size_t)(b * NKV + kv) * 4 + r);
    const float* pm = g_pm + hb * SPLITS + sg * SPG;
    const float* pl = g_pl + hb * SPLITS + sg * SPG;
    const float* pa = g_pacc + (hb * SPLITS + sg * SPG) * HD + d;

    float M = -1e30f;
#pragma unroll
    for (int s = 0; s < SPG; s++) M = fmaxf(M, pm[s]);
    float L = 0.f, acc = 0.f;
#pragma unroll
    for (int s = 0; s < SPG; s++) {
        float wgt = __expf(pm[s] - M);
        L += pl[s] * wgt;
        acc = fmaf(__ldcs(pa + (size_t)s * HD), wgt, acc);
    }
    sacc[sg][d] = acc;
    if (d == 0) { sM[sg] = M; sL[sg] = L; }
    __syncthreads();

    if (sg == 0) {
        float Mg = -1e30f;
#pragma unroll
        for (int g2 = 0; g2 < SGRP; g2++) Mg = fmaxf(Mg, sM[g2]);
        float Lg = 0.f, a = 0.f;
#pragma unroll
        for (int g2 = 0; g2 < SGRP; g2++) {
            float f = __expf(sM[g2] - Mg);
            Lg += sL[g2] * f;
            a = fmaf(sacc[g2][d], f, a);
        }
        g_attn[b * (NH * HD) + h * HD + d] = a / Lg;
    }
}

// ---------------- reduce wo-GEMM partials -> final out ----------------
__global__ void reduce_out_kernel(float* __restrict__ out) {
    int i = (blockIdx.x * 256 + threadIdx.x) * 4;
    float4 s = make_float4(0.f, 0.f, 0.f, 0.f);
#pragma unroll
    for (int ks = 0; ks < KSPLIT; ks++) {
        float4 p = __ldcs((const float4*)&g_opart[ks][i]);
        s.x += p.x; s.y += p.y; s.z += p.z; s.w += p.w;
    }
    *(float4*)(out + i) = s;
}

// ---------------- launch ----------------
extern "C" void kernel_launch(void* const* d_in, const int* in_sizes, int n_in,
                              void* d_out, int out_size) {
    const float* x       = (const float*)d_in[0];
    const float* mask    = (const float*)d_in[1];
    const float* rope    = (const float*)d_in[2];
    const float* wq      = (const float*)d_in[3];
    const float* wk      = (const float*)d_in[4];
    const float* wv      = (const float*)d_in[5];
    const float* wo      = (const float*)d_in[6];
    const float* cache_k = (const float*)d_in[7];
    const float* cache_v = (const float*)d_in[8];
    const int*   last_pos = (const int*)d_in[9];

    float* out   = (float*)d_out;
    float* out_k = out + (size_t)BS * HIDDEN;
    float* out_v = out_k + (size_t)BS * SEQ * NKV * HD;

    const int smem_bytes = 2 * 8 * DEPTH * 2 * 32 * 16 + 4 * HD * 4;  // 34 KB
    static int attr_set = 0;
    if (!attr_set) {
        cudaFuncSetAttribute(attn_kernel, cudaFuncAttributeMaxDynamicSharedMemorySize, smem_bytes);
        attr_set = 1;
    }

    qkv_gemm_kernel<<<dim3(QKV_N / 128, KSPLIT), 128>>>(x, wq, wk, wv);
    rope_reduce_kernel<<<(BS * QKV_N / 2) / 256, 256>>>(rope, last_pos);
    attn_kernel<<<dim3(SPLITS, NKV, BS), 256, smem_bytes>>>(cache_k, cache_v, mask, last_pos, out_k, out_v);
    combine_kernel<<<dim3(NH, BS), dim3(HD, SGRP)>>>();
    wo_gemm_kernel<<<dim3(HIDDEN / 128, KSPLIT), 128>>>(wo);
    reduce_out_kernel<<<(BS * HIDDEN / 4) / 256, 256>>>(out);
}